// round 12
// baseline (speedup 1.0000x reference)
#include <cuda_runtime.h>
#include <cuda_bf16.h>
#include <cstdint>
#include <cstddef>

typedef unsigned long long ull;

#define B_  64
#define S_  200
#define T_  199
#define H_  256
#define G4  1024
#define NI_ 50000

#define CL  8           // CTAs per cluster
#define NCL 16          // clusters (16*4 = 64 batches)
#define CPT 512         // compute threads
#define THR 640         // + 4 owner warps (one per subgroup)
#define BARCNT 544      // 512 compute + 32 owners of one subgroup
#define TXB 2048u       // expect_tx: 8 CTAs x 32 owners x 8B per subgroup
#define K1_BLOCKS 1592  // 1592*8 warps = 199*64 (b,t) pairs exactly

// ------------------------- device scratch (no allocs allowed) ---------------
__device__ __align__(16) float g_xp[(size_t)T_ * B_ * G4];      // xp + bias, [t][b][1024]
__device__ __align__(16) float g_states[(size_t)T_ * B_ * H_];  // masked h outputs [t][b][256]
__device__ unsigned char g_mask[T_ * B_];
__device__ unsigned g_k3done;
__device__ float2 g_part[K1_BLOCKS];

// ------------------------- helpers ------------------------------------------
__device__ __forceinline__ ull pk2(float lo, float hi) {
    ull r; asm("mov.b64 %0, {%1, %2};" : "=l"(r) : "f"(lo), "f"(hi)); return r;
}
__device__ __forceinline__ void upk2(ull v, float& lo, float& hi) {
    asm("mov.b64 {%0, %1}, %2;" : "=f"(lo), "=f"(hi) : "l"(v));
}
__device__ __forceinline__ void fma2(ull& acc, ull a, ull b) {
    asm("fma.rn.f32x2 %0, %1, %2, %0;" : "+l"(acc) : "l"(a), "l"(b));
}
__device__ __forceinline__ ull add2(ull a, ull b) {
    ull r; asm("add.rn.f32x2 %0, %1, %2;" : "=l"(r) : "l"(a), "l"(b)); return r;
}
__device__ __forceinline__ float tanha(float x) {
    float y; asm("tanh.approx.f32 %0, %1;" : "=f"(y) : "f"(x)); return y;
}
__device__ __forceinline__ float siga(float x) {
    return fmaf(tanha(0.5f * x), 0.5f, 0.5f);
}
__device__ __forceinline__ unsigned smem_u32(const void* p) {
    unsigned a;
    asm("{ .reg .u64 t; cvta.to.shared.u64 t, %1; cvt.u32.u64 %0, t; }" : "=r"(a) : "l"(p));
    return a;
}
__device__ __forceinline__ unsigned ctarank_() {
    unsigned r; asm("mov.u32 %0, %%cluster_ctarank;" : "=r"(r)); return r;
}
__device__ __forceinline__ unsigned mapa_(unsigned addr, unsigned rank) {
    unsigned r; asm("mapa.shared::cluster.u32 %0, %1, %2;" : "=r"(r) : "r"(addr), "r"(rank));
    return r;
}
__device__ __forceinline__ void mbar_init(unsigned addr, unsigned cnt) {
    asm volatile("mbarrier.init.shared.b64 [%0], %1;" :: "r"(addr), "r"(cnt) : "memory");
}
__device__ __forceinline__ void mbar_expect_tx(unsigned addr, unsigned bytes) {
    asm volatile("mbarrier.arrive.expect_tx.shared.b64 _, [%0], %1;"
                 :: "r"(addr), "r"(bytes) : "memory");
}
// remote store whose completion posts tx bytes on the destination CTA's barrier
__device__ __forceinline__ void st_async64(unsigned raddr, ull v, unsigned rmbar) {
    asm volatile("st.async.shared::cluster.mbarrier::complete_tx::bytes.b64 [%0], %1, [%2];"
                 :: "r"(raddr), "l"(v), "r"(rmbar) : "memory");
}
__device__ __forceinline__ void mbar_wait(unsigned addr, int parity) {
    asm volatile(
        "{\n\t.reg .pred P;\n\t"
        "WL_%=:\n\t"
        "mbarrier.try_wait.parity.acquire.cta.shared::cta.b64 P, [%0], %1, 0x989680;\n\t"
        "@P bra.uni WD_%=;\n\t"
        "bra.uni WL_%=;\n\t"
        "WD_%=:\n\t}"
        :: "r"(addr), "r"(parity) : "memory");
}
__device__ __forceinline__ void cluster_sync_() {
    asm volatile("barrier.cluster.arrive.aligned;" ::: "memory");
    asm volatile("barrier.cluster.wait.aligned;" ::: "memory");
}

// ============================================================================
// K1: x_proj (+bias) -> g_xp, mask bytes, reset k3 flag. One warp per (b,t).
// ============================================================================
__global__ void k1_prep(const int* __restrict__ items, const int* __restrict__ actions,
                        const float* __restrict__ WihT, const float* __restrict__ b_lstm) {
    if (blockIdx.x == 0 && threadIdx.x == 0) g_k3done = 0u;
    int gw = blockIdx.x * 8 + (threadIdx.x >> 5);
    int lane = threadIdx.x & 31;
    if (gw >= T_ * B_) return;
    int b = gw & 63, t = gw >> 6;
    int it = items[b * S_ + t];
    int ac = actions[b * S_ + t];
    bool m = (it != 0);
    const float4* ra = (const float4*)(WihT + (size_t)it * G4);
    const float4* rb = (const float4*)(WihT + (size_t)(NI_ + ac) * G4);
    const float4* bi = (const float4*)b_lstm;
    float4* dst = (float4*)(g_xp + ((size_t)t * B_ + b) * G4);
#pragma unroll
    for (int p = 0; p < 8; p++) {
        int idx = lane + 32 * p;
        float4 bv = bi[idx];
        float4 o;
        if (m) {
            float4 a = ra[idx], c = rb[idx];
            o = make_float4(a.x + c.x + bv.x, a.y + c.y + bv.y,
                            a.z + c.z + bv.z, a.w + c.w + bv.w);
        } else {
            o = bv;
        }
        dst[idx] = o;
    }
    if (lane == 0) g_mask[t * B_ + b] = m ? 1 : 0;
}

// profiling-alignment no-ops (2 launches so ncu -s 5 -c 1 lands on k2_lstm)
__global__ void knop() {}

// ============================================================================
// K2: 4-deep pipelined LSTM. 16 clusters x 8 CTAs; cluster owns 4 batches,
// subgroup sg owns batch b0+sg (1 batch). CTA rank r owns 128 gate rows
// (32 h-elems x 4 gates), K=256. Weights packed {col_u, col_u+64} so one
// fma2 serves 2 columns with the same broadcast h.
// smp[sg][ks][c] packs {i,g} (c<32+e) / {f,o} (c=32+e) gate pairs.
// Owners: 1 warp per subgroup; chain = bar.sync -> reduce -> act -> st.async.
// Re-arm done by compute lane tid==sg right after its wait (causally safe).
// ============================================================================
__global__ void __launch_bounds__(THR, 1) __cluster_dims__(CL, 1, 1)
k2_lstm(const float* __restrict__ Whh) {
    __shared__ __align__(16) ull smh[4][2][256];   // [sg][buf][j] = {h,h}
    __shared__ __align__(16) ull smp[4][8][128];   // [sg][ks][col-pair]
    __shared__ __align__(8)  ull mbar[4][2];       // [sg][buf]

    const int tid = threadIdx.x;
    const unsigned rank = ctarank_();
    const int b0 = (blockIdx.x >> 3) * 4;

    // zero h buffers (16 KB); init + pre-arm all 8 barriers
    for (int i = tid; i < 1024; i += THR)
        ((float4*)smh)[i] = make_float4(0.f, 0.f, 0.f, 0.f);
    if (tid < 8) mbar_init(smem_u32(&mbar[tid >> 1][tid & 1]), 1);
    __syncthreads();
    if (tid == 0) {
#pragma unroll
        for (int s = 0; s < 4; s++) {
            mbar_expect_tx(smem_u32(&mbar[s][0]), TXB);
            mbar_expect_tx(smem_u32(&mbar[s][1]), TXB);
        }
    }
    __syncthreads();
    cluster_sync_();   // arming + zeroed tiles visible before any peer store

    if (tid < CPT) {
        // ---------------- compute role ----------------
        const int ks = tid >> 6;    // K-slice: j in [32ks, 32ks+32)
        const int u  = tid & 63;    // packed cols {u, u+64}

        // Wpk[j] = {Whh[row(u)][ks*32+j], Whh[row(u+64)][ks*32+j]}
        ull Wpk[32];
        {
            const int r1 = (u >> 5) * 256 + 32 * (int)rank + (u & 31);
            const int r2 = (2 + (u >> 5)) * 256 + 32 * (int)rank + (u & 31);
            const float4* p1 = (const float4*)(Whh + (size_t)r1 * H_ + ks * 32);
            const float4* p2 = (const float4*)(Whh + (size_t)r2 * H_ + ks * 32);
#pragma unroll
            for (int q4 = 0; q4 < 8; q4++) {
                float4 v = p1[q4];
                float4 w = p2[q4];
                Wpk[q4 * 4 + 0] = pk2(v.x, w.x);
                Wpk[q4 * 4 + 1] = pk2(v.y, w.y);
                Wpk[q4 * 4 + 2] = pk2(v.z, w.z);
                Wpk[q4 * 4 + 3] = pk2(v.w, w.w);
            }
        }

        for (int t = 0; t < T_; t++) {
            const int buf = t & 1;
            const int par = ((t >> 1) + (t & 1) + 1) & 1;
#pragma unroll
            for (int sg = 0; sg < 4; sg++) {
                if (t > 0) {
                    const unsigned mb = smem_u32(&mbar[sg][buf]);
                    mbar_wait(mb, par);
                    if (tid == sg) mbar_expect_tx(mb, TXB);  // re-arm for t+2
                }
                ull a = 0, b = 0;
                {
                    const ulonglong2* hb = (const ulonglong2*)&smh[sg][buf][ks * 32];
#pragma unroll
                    for (int j2 = 0; j2 < 16; j2++) {
                        ulonglong2 hx = hb[j2];   // {h_j,h_j},{h_j+1,h_j+1}
                        fma2(a, Wpk[2 * j2],     hx.x);
                        fma2(b, Wpk[2 * j2 + 1], hx.y);
                    }
                }
                smp[sg][ks][u] = add2(a, b);
                asm volatile("bar.arrive %0, %1;" :: "r"(2 + sg), "n"(BARCNT) : "memory");
            }
        }
    } else {
        // ---------------- owner role: warp per subgroup ----------------
        const int ot = tid - CPT;          // 0..127
        const int sg = ot >> 5;            // subgroup = batch
        const int e  = ot & 31;            // h-elem within CTA
        const int bA = b0 + sg;
        const int jg = 32 * (int)rank + e; // global h index owned

        float cst = 0.f, hst = 0.f;
        unsigned char mk = g_mask[bA];
        const float* xb = g_xp + (size_t)bA * G4 + jg;   // + gate*256
        float xpi = xb[0], xpf = xb[256], xpg = xb[512], xpo = xb[768];

        // precompute remote addresses (both bufs) + remote barrier addrs
        unsigned locs[2][CL], mbns[2][CL];
        {
            unsigned l0 = smem_u32(&smh[sg][0][jg]);
            unsigned l1 = smem_u32(&smh[sg][1][jg]);
            unsigned m0 = smem_u32(&mbar[sg][0]);
            unsigned m1 = smem_u32(&mbar[sg][1]);
#pragma unroll
            for (int rr = 0; rr < CL; rr++) {
                locs[0][rr] = mapa_(l0, rr);
                locs[1][rr] = mapa_(l1, rr);
                mbns[0][rr] = mapa_(m0, rr);
                mbns[1][rr] = mapa_(m1, rr);
            }
        }

        for (int t = 0; t < T_; t++) {
            const int buf = t & 1;
            asm volatile("bar.sync %0, %1;" :: "r"(2 + sg), "n"(BARCNT) : "memory");

            // reduce 8 K-slices of packed gate pairs (16 LDS.64 + 14 add2)
            ull sig2 = smp[sg][0][e], sfo2 = smp[sg][0][32 + e];
#pragma unroll
            for (int k = 1; k < 8; k++) {
                sig2 = add2(sig2, smp[sg][k][e]);
                sfo2 = add2(sfo2, smp[sg][k][32 + e]);
            }
            sig2 = add2(sig2, pk2(xpi, xpg));
            sfo2 = add2(sfo2, pk2(xpf, xpo));

            float iv, gv, fv, ov;
            upk2(sig2, iv, gv);
            upk2(sfo2, fv, ov);

            float ii = siga(iv), ff = siga(fv), gt = tanha(gv), oo = siga(ov);
            float cn = ff * cst + ii * gt;
            float hn = oo * tanha(cn);
            float out;
            if (mk) { cst = cn; hst = hn; out = hn; } else out = 0.f;

            // broadcast h(t+1) first (critical path)
            if (t + 1 < T_) {
                ull hull = pk2(hst, hst);
#pragma unroll
                for (int rr = 0; rr < CL; rr++)
                    st_async64(locs[1 - buf][rr], hull, mbns[1 - buf][rr]);
            }

            // off critical path: states store + next-step prefetch
            g_states[((size_t)t * B_ + bA) * H_ + jg] = out;
            if (t + 1 < T_) {
                const float* xp = xb + (size_t)(t + 1) * B_ * G4;
                xpi = xp[0]; xpf = xp[256]; xpg = xp[512]; xpo = xp[768];
                mk = g_mask[(t + 1) * B_ + bA];
            }
        }
    }
    cluster_sync_();  // no CTA exits while peers' remote ops may be in flight
}

// ============================================================================
// K3: query logits + per-(b,t) NLL; block partials + fused deterministic
// last-block final reduction. One warp per (b,t).
// ============================================================================
__global__ void k3_loss(const int* __restrict__ items, const int* __restrict__ actions,
                        const float* __restrict__ temb, const float* __restrict__ Wq,
                        const float* __restrict__ bq, float* __restrict__ out) {
    __shared__ float2 sred[8];
    __shared__ unsigned slast;
    int gw = blockIdx.x * 8 + (threadIdx.x >> 5);
    int lane = threadIdx.x & 31;
    float nll = 0.f, cnt = 0.f;
    int b = gw & 63, t = gw >> 6;
    int qit = items[b * S_ + t + 1];
    if (qit != 0) {
        const float4* sv = (const float4*)(g_states + ((size_t)t * B_ + b) * H_);
        const float4* ev = (const float4*)(temb + (size_t)qit * H_);
        const float4* w0 = (const float4*)Wq;
        const float4* w1 = (const float4*)(Wq + H_);
        float d0 = 0.f, d1 = 0.f;
#pragma unroll
        for (int p = 0; p < 2; p++) {
            int idx = lane * 2 + p;
            float4 s = sv[idx], e = ev[idx], a = w0[idx], c = w1[idx];
            float es;
            es = e.x * s.x; d0 += es * a.x; d1 += es * c.x;
            es = e.y * s.y; d0 += es * a.y; d1 += es * c.y;
            es = e.z * s.z; d0 += es * a.z; d1 += es * c.z;
            es = e.w * s.w; d0 += es * a.w; d1 += es * c.w;
        }
        ull d = pk2(d0, d1);
#pragma unroll
        for (int off = 16; off; off >>= 1)
            d = add2(d, __shfl_xor_sync(0xffffffffu, d, off));
        upk2(d, d0, d1);
        if (lane == 0) {
            float q0 = d0 + bq[0], q1 = d1 + bq[1];
            int tgt = actions[b * S_ + t + 1];
            float mx = fmaxf(q0, q1), mn = fminf(q0, q1);
            float lse = mx + log1pf(__expf(mn - mx));
            nll = lse - (tgt ? q1 : q0);
            cnt = 1.f;
        }
    }
    if (lane == 0) sred[threadIdx.x >> 5] = make_float2(nll, cnt);
    __syncthreads();
    if (threadIdx.x == 0) {
        float s = 0.f, c = 0.f;
#pragma unroll
        for (int i = 0; i < 8; i++) { s += sred[i].x; c += sred[i].y; }
        g_part[blockIdx.x] = make_float2(s, c);
        __threadfence();
        unsigned o = atomicAdd(&g_k3done, 1u);
        slast = (o == K1_BLOCKS - 1) ? 1u : 0u;
    }
    __syncthreads();
    if (slast) {
        __shared__ float ss[256], sc[256];
        __threadfence();
        float s = 0.f, c = 0.f;
        for (int i = threadIdx.x; i < K1_BLOCKS; i += 256) {
            float2 v = g_part[i];
            s += v.x; c += v.y;
        }
        ss[threadIdx.x] = s; sc[threadIdx.x] = c;
        __syncthreads();
        for (int st = 128; st; st >>= 1) {
            if (threadIdx.x < st) {
                ss[threadIdx.x] += ss[threadIdx.x + st];
                sc[threadIdx.x] += sc[threadIdx.x + st];
            }
            __syncthreads();
        }
        if (threadIdx.x == 0) out[0] = ss[0] / sc[0];
    }
}

// ============================================================================
extern "C" void kernel_launch(void* const* d_in, const int* in_sizes, int n_in,
                              void* d_out, int out_size) {
    const int*   items   = (const int*)d_in[0];
    const int*   actions = (const int*)d_in[1];
    const float* WihT    = (const float*)d_in[2];
    const float* Whh     = (const float*)d_in[3];
    const float* b_lstm  = (const float*)d_in[4];
    const float* temb    = (const float*)d_in[5];
    const float* Wq      = (const float*)d_in[6];
    const float* bq      = (const float*)d_in[7];
    (void)in_sizes; (void)n_in; (void)out_size;

    k1_prep<<<K1_BLOCKS, 256>>>(items, actions, WihT, b_lstm);
    knop<<<1, 1>>>();   // alignment: put k2_lstm at ncu's profiled slot (-s 5)
    knop<<<1, 1>>>();
    k2_lstm<<<NCL * CL, THR>>>(Whh);
    k3_loss<<<K1_BLOCKS, 256>>>(items, actions, temb, Wq, bq, (float*)d_out);
}